// round 1
// baseline (speedup 1.0000x reference)
#include <cuda_runtime.h>
#include <cuda_bf16.h>

#define L_  1024
#define DM  1024
#define DI  2048
#define NS  16
#define DR  64
#define BB  2

// ---------------- scratch (static device globals; no allocation) -------------
__device__ float g_hid_t [BB*DI*L_];   // hidden, (b, d, t)
__device__ float g_gate_t[BB*DI*L_];   // gate,   (b, d, t)
__device__ float g_ssm   [BB*L_*96];   // (b*t, 96): [0:64)=dt_pre, [64:80)=B, [80:96)=C
__device__ float g_dt_t  [BB*DI*L_];   // softplus(dt), (b, d, t)
__device__ float g_so_t  [BB*DI*L_];   // scan output pre-out_proj, (b, d, t)

__device__ __forceinline__ float softplusf(float x) {
    return x > 20.f ? x : log1pf(__expf(x));
}

// ---------------- generic tiled FP32 GEMM: C[m,n] = sum_k A[m,k] * W[n,k] ----
// EPI: 0 = in_proj split->hid_t/gate_t (transposed write)
//      1 = x_proj -> g_ssm
//      2 = dt_proj + bias + softplus -> g_dt_t (transposed write)
//      3 = out_proj -> Out (row-major)
// AKMAJ: A stored K-major as (b, k, t) with m = b*1024 + t
// ASRC:  0 = Aarg, 1 = g_hid_t, 2 = g_ssm, 3 = g_so_t
template<int EPI, bool AKMAJ, int ASRC>
__global__ __launch_bounds__(256)
void gemm_k(const float* __restrict__ Aarg, const float* __restrict__ W,
            float* __restrict__ Out, int M, int N, int K, int lda,
            const float* __restrict__ bias)
{
    const float* A = (ASRC == 0) ? Aarg :
                     (ASRC == 1) ? g_hid_t :
                     (ASRC == 2) ? g_ssm  : g_so_t;

    __shared__ __align__(16) float As[16][68];
    __shared__ __align__(16) float Bs[16][68];

    int tid = threadIdx.x;
    int n0 = blockIdx.x * 64;
    int m0 = blockIdx.y * 64;
    int tr = tid >> 4;     // 0..15
    int tc = tid & 15;     // 0..15

    float acc[4][4] = {};

    for (int k0 = 0; k0 < K; k0 += 16) {
        if (AKMAJ) {
            #pragma unroll
            for (int i = 0; i < 4; i++) {
                int li = tid + i * 256;
                int m = li & 63, k = li >> 6;
                int gm = m0 + m;
                As[k][m] = A[(((gm >> 10) * K) + k0 + k) * L_ + (gm & 1023)];
            }
        } else {
            #pragma unroll
            for (int i = 0; i < 4; i++) {
                int li = tid + i * 256;
                int k = li & 15, m = li >> 4;
                As[k][m] = A[(m0 + m) * lda + k0 + k];
            }
        }
        #pragma unroll
        for (int i = 0; i < 4; i++) {
            int li = tid + i * 256;
            int k = li & 15, n = li >> 4;
            int gn = n0 + n;
            Bs[k][n] = (gn < N) ? W[gn * K + k0 + k] : 0.f;
        }
        __syncthreads();
        #pragma unroll
        for (int k = 0; k < 16; k++) {
            float4 av = *(const float4*)&As[k][tr * 4];
            float4 bv = *(const float4*)&Bs[k][tc * 4];
            float a4[4] = {av.x, av.y, av.z, av.w};
            float b4[4] = {bv.x, bv.y, bv.z, bv.w};
            #pragma unroll
            for (int i = 0; i < 4; i++)
                #pragma unroll
                for (int j = 0; j < 4; j++)
                    acc[i][j] = fmaf(a4[i], b4[j], acc[i][j]);
        }
        __syncthreads();
    }

    #pragma unroll
    for (int i = 0; i < 4; i++) {
        int gm = m0 + tr * 4 + i;
        int b = gm >> 10, t = gm & 1023;
        #pragma unroll
        for (int j = 0; j < 4; j++) {
            int gn = n0 + tc * 4 + j;
            float v = acc[i][j];
            if (EPI == 0) {
                if (gn < DI) g_hid_t [((b * DI) + gn)        * L_ + t] = v;
                else         g_gate_t[((b * DI) + (gn - DI)) * L_ + t] = v;
            } else if (EPI == 1) {
                if (gn < N) g_ssm[gm * 96 + gn] = v;
            } else if (EPI == 2) {
                v = softplusf(v + bias[gn]);
                g_dt_t[((b * DI) + gn) * L_ + t] = v;
            } else {
                Out[gm * N + gn] = v;
            }
        }
    }
}

// ---------------- bidirectional selective scan -------------------------------
// One warp per (b, d). Lanes 0-15: forward recurrence (state n = lane).
// Lanes 16-31: backward recurrence (state n = lane-16), t descending, using
// prev-iteration 'a' (= a_{t+1}).   feature = fwd + bwd - u, y = sum_n C*feature.
__global__ __launch_bounds__(128)
void scan_k(const float* __restrict__ A_log, const float* __restrict__ Dp)
{
    __shared__ float ys[4][L_];
    int warp  = (blockIdx.x * blockDim.x + threadIdx.x) >> 5;  // 0..4095
    int lane  = threadIdx.x & 31;
    int wloc  = threadIdx.x >> 5;
    int b = warp >> 11;
    int d = warp & (DI - 1);
    int n = lane & 15;
    bool fw = lane < 16;

    const float* dtp   = g_dt_t  + ((size_t)b * DI + d) * L_;
    const float* hp    = g_hid_t + ((size_t)b * DI + d) * L_;
    const float* ssm_b = g_ssm   + (size_t)b * L_ * 96;

    float An = -__expf(A_log[d * NS + n]);
    float* y = ys[wloc];
    for (int t = lane; t < L_; t += 32) y[t] = 0.f;
    __syncwarp();

    float s = 0.f, pa = 0.f;
    for (int i = 0; i < L_; i++) {
        int t = fw ? i : (L_ - 1 - i);
        float dtv = dtp[t];
        float h   = hp[t];
        float a   = __expf(An * dtv);
        float Bv  = ssm_b[t * 96 + 64 + n];
        float Cv  = ssm_b[t * 96 + 80 + n];
        float u   = dtv * Bv * h;

        float coef = fw ? a : pa;
        s = fmaf(coef, s, u);
        float base = fw ? s : (s - u);
        float contrib = Cv * base;
        pa = a;

        contrib += __shfl_xor_sync(0xffffffffu, contrib, 8);
        contrib += __shfl_xor_sync(0xffffffffu, contrib, 4);
        contrib += __shfl_xor_sync(0xffffffffu, contrib, 2);
        contrib += __shfl_xor_sync(0xffffffffu, contrib, 1);
        if (n == 0) y[t] += contrib;   // lane0 (fwd,t=i) and lane16 (bwd,t=1023-i): disjoint t
    }
    __syncwarp();

    float Dv = Dp[d];
    const float* gp  = g_gate_t + ((size_t)b * DI + d) * L_;
    float*       sop = g_so_t   + ((size_t)b * DI + d) * L_;
    for (int t = lane; t < L_; t += 32) {
        float g   = gp[t];
        float sil = g / (1.f + __expf(-g));
        sop[t] = (1.3f * y[t] + hp[t] * Dv) * sil;
    }
}

// ---------------- launch -----------------------------------------------------
extern "C" void kernel_launch(void* const* d_in, const int* in_sizes, int n_in,
                              void* d_out, int out_size)
{
    const float* x      = (const float*)d_in[0];  // (2,1024,1024)
    const float* w_in   = (const float*)d_in[1];  // (4096,1024)
    const float* w_x    = (const float*)d_in[2];  // (96,2048)
    const float* w_dt   = (const float*)d_in[3];  // (2048,64)
    const float* b_dt   = (const float*)d_in[4];  // (2048,)
    const float* A_log  = (const float*)d_in[5];  // (2048,16)
    const float* Dvec   = (const float*)d_in[6];  // (2048,)
    const float* w_out  = (const float*)d_in[7];  // (1024,2048)
    float* out = (float*)d_out;                   // (2,1024,1024)

    const int M = BB * L_;  // 2048

    // 1) in_proj: (2048x1024) @ (4096x1024)^T -> hidden_t + gate_t (transposed)
    gemm_k<0, false, 0><<<dim3(4096 / 64, M / 64), 256>>>(x, w_in, nullptr, M, 2 * DI, DM, DM, nullptr);
    // 2) x_proj: hidden (K-major) @ (96x2048)^T -> g_ssm
    gemm_k<1, true, 1><<<dim3(2, M / 64), 256>>>(nullptr, w_x, nullptr, M, 96, DI, 0, nullptr);
    // 3) dt_proj: ssm[:, :64] @ (2048x64)^T + b, softplus -> g_dt_t (transposed)
    gemm_k<2, false, 2><<<dim3(DI / 64, M / 64), 256>>>(nullptr, w_dt, nullptr, M, DI, DR, 96, b_dt);
    // 4) bidirectional scan + gating -> g_so_t
    scan_k<<<(BB * DI) / 4, 128>>>(A_log, Dvec);
    // 5) out_proj: so (K-major) @ (1024x2048)^T -> out
    gemm_k<3, true, 3><<<dim3(DM / 64, M / 64), 256>>>(nullptr, w_out, out, M, DM, DI, 0, nullptr);
}

// round 2
// speedup vs baseline: 1.8992x; 1.8992x over previous
#include <cuda_runtime.h>
#include <cuda_bf16.h>

#define L_  1024
#define DM  1024
#define DI  2048
#define NS  16
#define DR  64
#define BB  2
#define CH  8
#define CT  (L_/CH)                 // 128 steps per chunk
#define CARRY_N (BB*DI*2*NS)        // 131072

// ---------------- scratch (static device globals; no allocation) -------------
__device__ float g_hid_t [BB*DI*L_];   // hidden, (b, d, t)
__device__ float g_gate_t[BB*DI*L_];   // gate,   (b, d, t)
__device__ float g_ssm   [BB*L_*96];   // (b*t, 96): [0:64)=dt_pre, [64:80)=B, [80:96)=C
__device__ float g_dt_t  [BB*DI*L_];   // softplus(dt), (b, d, t)
__device__ float g_so_t  [BB*DI*L_];   // scan output pre-out_proj, (b, d, t)
__device__ float g_P   [CH*CARRY_N];   // chunk operator: product of coefs
__device__ float g_S   [CH*CARRY_N];   // chunk operator: local final state
__device__ float g_cin [CH*CARRY_N];   // carry-in state per chunk

__device__ __forceinline__ float softplusf(float x) {
    return x > 20.f ? x : log1pf(__expf(x));
}

// =============================================================================
//  Big GEMM: 128x128 tile, BK=16, 256 threads, 8x8 microtile
// =============================================================================

// GEMM1: hidden/gate = x @ w_in^T, transposed-split write into (b,d,t) layout
__global__ __launch_bounds__(256, 2)
void gemm_in(const float* __restrict__ A, const float* __restrict__ W)
{
    __shared__ __align__(16) float As[16][132];
    __shared__ __align__(16) float Bs[16][132];
    const int K = DM;
    int tid = threadIdx.x;
    int n0 = blockIdx.x * 128;
    int m0 = blockIdx.y * 128;
    int tx = tid & 15, ty = tid >> 4;
    float acc[8][8] = {};

    for (int k0 = 0; k0 < K; k0 += 16) {
        #pragma unroll
        for (int r = 0; r < 2; r++) {
            int li = tid + r * 256;
            int m  = li >> 2;
            int kq = (li & 3) * 4;
            float4 fa = *(const float4*)&A[(size_t)(m0 + m) * K + k0 + kq];
            As[kq+0][m] = fa.x; As[kq+1][m] = fa.y; As[kq+2][m] = fa.z; As[kq+3][m] = fa.w;
            float4 fb = *(const float4*)&W[(size_t)(n0 + m) * K + k0 + kq];
            Bs[kq+0][m] = fb.x; Bs[kq+1][m] = fb.y; Bs[kq+2][m] = fb.z; Bs[kq+3][m] = fb.w;
        }
        __syncthreads();
        #pragma unroll
        for (int k = 0; k < 16; k++) {
            float a[8], b[8];
            *(float4*)&a[0] = *(const float4*)&As[k][ty*8];
            *(float4*)&a[4] = *(const float4*)&As[k][ty*8+4];
            *(float4*)&b[0] = *(const float4*)&Bs[k][tx*8];
            *(float4*)&b[4] = *(const float4*)&Bs[k][tx*8+4];
            #pragma unroll
            for (int i = 0; i < 8; i++)
                #pragma unroll
                for (int j = 0; j < 8; j++)
                    acc[i][j] = fmaf(a[i], b[j], acc[i][j]);
        }
        __syncthreads();
    }

    int bb = m0 >> 10;              // m-tile lies entirely in one batch (1024%128==0)
    int t0 = m0 & 1023;
    float* dst = (n0 < DI) ? g_hid_t : g_gate_t;
    int nb = (n0 < DI) ? n0 : n0 - DI;
    #pragma unroll
    for (int i = 0; i < 8; i++) {
        int t = t0 + ty * 8 + i;
        #pragma unroll
        for (int j = 0; j < 8; j++) {
            int col = nb + tx * 8 + j;
            dst[((size_t)bb * DI + col) * L_ + t] = acc[i][j];
        }
    }
}

// GEMM5: out = so @ w_out^T, A read K-major from g_so_t, row-major write
__global__ __launch_bounds__(256, 2)
void gemm_out(const float* __restrict__ W, float* __restrict__ Out)
{
    __shared__ __align__(16) float As[16][132];
    __shared__ __align__(16) float Bs[16][132];
    const int K = DI;   // 2048
    const int N = DM;   // 1024
    int tid = threadIdx.x;
    int n0 = blockIdx.x * 128;
    int m0 = blockIdx.y * 128;
    int bb = m0 >> 10;
    int t0 = m0 & 1023;
    int tx = tid & 15, ty = tid >> 4;
    float acc[8][8] = {};

    for (int k0 = 0; k0 < K; k0 += 16) {
        // A: K-major (b, k, t) — coalesced float4 along t
        #pragma unroll
        for (int r = 0; r < 2; r++) {
            int li = tid + r * 256;
            int m4 = (li & 31) * 4;
            int k  = li >> 5;
            float4 fa = *(const float4*)&g_so_t[((size_t)bb * DI + k0 + k) * L_ + t0 + m4];
            *(float4*)&As[k][m4] = fa;
        }
        // W: row-major (N, K) — transpose on load
        #pragma unroll
        for (int r = 0; r < 2; r++) {
            int li = tid + r * 256;
            int n  = li >> 2;
            int kq = (li & 3) * 4;
            float4 fb = *(const float4*)&W[(size_t)(n0 + n) * K + k0 + kq];
            Bs[kq+0][n] = fb.x; Bs[kq+1][n] = fb.y; Bs[kq+2][n] = fb.z; Bs[kq+3][n] = fb.w;
        }
        __syncthreads();
        #pragma unroll
        for (int k = 0; k < 16; k++) {
            float a[8], b[8];
            *(float4*)&a[0] = *(const float4*)&As[k][ty*8];
            *(float4*)&a[4] = *(const float4*)&As[k][ty*8+4];
            *(float4*)&b[0] = *(const float4*)&Bs[k][tx*8];
            *(float4*)&b[4] = *(const float4*)&Bs[k][tx*8+4];
            #pragma unroll
            for (int i = 0; i < 8; i++)
                #pragma unroll
                for (int j = 0; j < 8; j++)
                    acc[i][j] = fmaf(a[i], b[j], acc[i][j]);
        }
        __syncthreads();
    }

    #pragma unroll
    for (int i = 0; i < 8; i++) {
        size_t row = (size_t)(m0 + ty * 8 + i) * N + n0 + tx * 8;
        float4 v0 = make_float4(acc[i][0], acc[i][1], acc[i][2], acc[i][3]);
        float4 v1 = make_float4(acc[i][4], acc[i][5], acc[i][6], acc[i][7]);
        *(float4*)&Out[row]     = v0;
        *(float4*)&Out[row + 4] = v1;
    }
}

// =============================================================================
//  Small GEMM (old 64x64 kernel) for x_proj / dt_proj
// =============================================================================
// EPI: 1 = x_proj -> g_ssm ; 2 = dt_proj + bias + softplus -> g_dt_t
// AKMAJ: A stored K-major as (b, k, t) with m = b*1024 + t
template<int EPI, bool AKMAJ, int ASRC>
__global__ __launch_bounds__(256)
void gemm_k(const float* __restrict__ W, int M, int N, int K, int lda,
            const float* __restrict__ bias)
{
    const float* A = (ASRC == 1) ? g_hid_t : g_ssm;

    __shared__ __align__(16) float As[16][68];
    __shared__ __align__(16) float Bs[16][68];

    int tid = threadIdx.x;
    int n0 = blockIdx.x * 64;
    int m0 = blockIdx.y * 64;
    int tr = tid >> 4;
    int tc = tid & 15;
    float acc[4][4] = {};

    for (int k0 = 0; k0 < K; k0 += 16) {
        if (AKMAJ) {
            #pragma unroll
            for (int i = 0; i < 4; i++) {
                int li = tid + i * 256;
                int m = li & 63, k = li >> 6;
                int gm = m0 + m;
                As[k][m] = A[(((gm >> 10) * K) + k0 + k) * L_ + (gm & 1023)];
            }
        } else {
            #pragma unroll
            for (int i = 0; i < 4; i++) {
                int li = tid + i * 256;
                int k = li & 15, m = li >> 4;
                As[k][m] = A[(m0 + m) * lda + k0 + k];
            }
        }
        #pragma unroll
        for (int i = 0; i < 4; i++) {
            int li = tid + i * 256;
            int k = li & 15, n = li >> 4;
            int gn = n0 + n;
            Bs[k][n] = (gn < N) ? W[gn * K + k0 + k] : 0.f;
        }
        __syncthreads();
        #pragma unroll
        for (int k = 0; k < 16; k++) {
            float4 av = *(const float4*)&As[k][tr * 4];
            float4 bv = *(const float4*)&Bs[k][tc * 4];
            float a4[4] = {av.x, av.y, av.z, av.w};
            float b4[4] = {bv.x, bv.y, bv.z, bv.w};
            #pragma unroll
            for (int i = 0; i < 4; i++)
                #pragma unroll
                for (int j = 0; j < 4; j++)
                    acc[i][j] = fmaf(a4[i], b4[j], acc[i][j]);
        }
        __syncthreads();
    }

    #pragma unroll
    for (int i = 0; i < 4; i++) {
        int gm = m0 + tr * 4 + i;
        int b = gm >> 10, t = gm & 1023;
        #pragma unroll
        for (int j = 0; j < 4; j++) {
            int gn = n0 + tc * 4 + j;
            float v = acc[i][j];
            if (EPI == 1) {
                if (gn < N) g_ssm[gm * 96 + gn] = v;
            } else {
                v = softplusf(v + bias[gn]);
                g_dt_t[((b * DI) + gn) * L_ + t] = v;
            }
        }
    }
}

// =============================================================================
//  Chunked bidirectional scan
//  fwd: s_t = a_t s_{t-1} + u_t ; bwd: s_t = a_{t+1} s_{t+1} + u_t (a_L := 0)
// =============================================================================

// Phase A: per-chunk operator (P = prod coef, S = local final state)
__global__ __launch_bounds__(128)
void scanA(const float* __restrict__ A_log)
{
    int gw   = blockIdx.x * 4 + (threadIdx.x >> 5);
    int lane = threadIdx.x & 31;
    int c = gw & 7;
    int d = (gw >> 3) & (DI - 1);
    int b = gw >> 14;
    int n = lane & 15;
    bool fw = lane < 16;

    const float* dtp = g_dt_t  + ((size_t)b * DI + d) * L_;
    const float* hp  = g_hid_t + ((size_t)b * DI + d) * L_;
    const float* ssm = g_ssm   + (size_t)b * L_ * 96;
    float An = -__expf(A_log[d * NS + n]);

    int lo = c * CT, hi = lo + CT - 1;
    float s = 0.f, P = 1.f;
    float pb = (hi + 1 < L_) ? __expf(An * dtp[hi + 1]) : 0.f;   // a_{hi+1}

    for (int i = 0; i < CT; i++) {
        int t = fw ? lo + i : hi - i;
        float dtv = dtp[t];
        float h   = hp[t];
        float a   = __expf(An * dtv);
        float Bv  = ssm[t * 96 + 64 + n];
        float u   = dtv * Bv * h;
        float coef = fw ? a : pb;
        s = fmaf(coef, s, u);
        P *= coef;
        pb = a;
    }
    int idx = ((b * DI + d) * 2 + (fw ? 0 : 1)) * NS + n;
    g_P[c * CARRY_N + idx] = P;
    g_S[c * CARRY_N + idx] = s;
}

// Phase B: serial combine over 8 chunks -> carry-in per chunk
__global__ void scanB()
{
    int idx = blockIdx.x * blockDim.x + threadIdx.x;  // < CARRY_N
    int dir = (idx >> 4) & 1;
    float cin = 0.f;
    if (dir == 0) {
        #pragma unroll
        for (int c = 0; c < CH; c++) {
            g_cin[c * CARRY_N + idx] = cin;
            cin = fmaf(g_P[c * CARRY_N + idx], cin, g_S[c * CARRY_N + idx]);
        }
    } else {
        #pragma unroll
        for (int c = CH - 1; c >= 0; c--) {
            g_cin[c * CARRY_N + idx] = cin;
            cin = fmaf(g_P[c * CARRY_N + idx], cin, g_S[c * CARRY_N + idx]);
        }
    }
}

// Phase C: seeded re-scan + C-reduction + gating epilogue
__global__ __launch_bounds__(128)
void scanC(const float* __restrict__ A_log, const float* __restrict__ Dp)
{
    __shared__ float ys[4][CT];
    int wloc = threadIdx.x >> 5;
    int gw   = blockIdx.x * 4 + wloc;
    int lane = threadIdx.x & 31;
    int c = gw & 7;
    int d = (gw >> 3) & (DI - 1);
    int b = gw >> 14;
    int n = lane & 15;
    bool fw = lane < 16;

    size_t off = ((size_t)b * DI + d) * L_;
    const float* dtp = g_dt_t  + off;
    const float* hp  = g_hid_t + off;
    const float* ssm = g_ssm   + (size_t)b * L_ * 96;
    float An = -__expf(A_log[d * NS + n]);

    int lo = c * CT, hi = lo + CT - 1;
    float* y = ys[wloc];
    for (int tt = lane; tt < CT; tt += 32) y[tt] = 0.f;
    __syncwarp();

    int idx = ((b * DI + d) * 2 + (fw ? 0 : 1)) * NS + n;
    float s  = g_cin[c * CARRY_N + idx];
    float pb = (hi + 1 < L_) ? __expf(An * dtp[hi + 1]) : 0.f;

    for (int i = 0; i < CT; i++) {
        int t = fw ? lo + i : hi - i;
        float dtv = dtp[t];
        float h   = hp[t];
        float a   = __expf(An * dtv);
        float Bv  = ssm[t * 96 + 64 + n];
        float Cv  = ssm[t * 96 + 80 + n];
        float u   = dtv * Bv * h;
        float coef = fw ? a : pb;
        s = fmaf(coef, s, u);
        float base = fw ? s : (s - u);     // bwd contributes s_bwd - u (u counted once)
        float contrib = Cv * base;
        pb = a;

        contrib += __shfl_xor_sync(0xffffffffu, contrib, 8);
        contrib += __shfl_xor_sync(0xffffffffu, contrib, 4);
        contrib += __shfl_xor_sync(0xffffffffu, contrib, 2);
        contrib += __shfl_xor_sync(0xffffffffu, contrib, 1);
        if (n == 0) y[fw ? i : CT - 1 - i] += contrib;   // disjoint slots per step
    }
    __syncwarp();

    float Dv = Dp[d];
    const float* gp = g_gate_t + off;
    for (int tt = lane; tt < CT; tt += 32) {
        int t = lo + tt;
        float g   = gp[t];
        float sil = g / (1.f + __expf(-g));
        g_so_t[off + t] = (1.3f * y[tt] + hp[t] * Dv) * sil;
    }
}

// ---------------- launch -----------------------------------------------------
extern "C" void kernel_launch(void* const* d_in, const int* in_sizes, int n_in,
                              void* d_out, int out_size)
{
    const float* x      = (const float*)d_in[0];  // (2,1024,1024)
    const float* w_in   = (const float*)d_in[1];  // (4096,1024)
    const float* w_x    = (const float*)d_in[2];  // (96,2048)
    const float* w_dt   = (const float*)d_in[3];  // (2048,64)
    const float* b_dt   = (const float*)d_in[4];  // (2048,)
    const float* A_log  = (const float*)d_in[5];  // (2048,16)
    const float* Dvec   = (const float*)d_in[6];  // (2048,)
    const float* w_out  = (const float*)d_in[7];  // (1024,2048)
    float* out = (float*)d_out;                   // (2,1024,1024)

    const int M = BB * L_;  // 2048

    // 1) in_proj (big GEMM, 128x128 tiles)
    gemm_in<<<dim3(4096 / 128, M / 128), 256>>>(x, w_in);
    // 2) x_proj: hidden (K-major) @ (96x2048)^T -> g_ssm
    gemm_k<1, true, 1><<<dim3(2, M / 64), 256>>>(w_x, M, 96, DI, 0, nullptr);
    // 3) dt_proj: ssm[:, :64] @ (2048x64)^T + b, softplus -> g_dt_t
    gemm_k<2, false, 2><<<dim3(DI / 64, M / 64), 256>>>(w_dt, M, DI, DR, 96, b_dt);
    // 4) chunked bidirectional scan
    scanA<<<BB * DI * CH / 4, 128>>>(A_log);
    scanB<<<CARRY_N / 256, 256>>>();
    scanC<<<BB * DI * CH / 4, 128>>>(A_log, Dvec);
    // 5) out_proj (big GEMM)
    gemm_out<<<dim3(DM / 128, M / 128), 256>>>(w_out, out);
}